// round 6
// baseline (speedup 1.0000x reference)
#include <cuda_runtime.h>
#include <cuda_fp16.h>
#include <stdint.h>
#include <math.h>

// ---------------------------------------------------------------------------
// Problem dims
// ---------------------------------------------------------------------------
#define B_SZ   16384
#define D_IN   1280
#define D_HID  512
#define D_OUT  229
#define K1     (7 * D_IN)    // 8960
#define K2     (7 * D_HID)   // 3584
#define N2PAD  256

// ---------------------------------------------------------------------------
// Scratch
// ---------------------------------------------------------------------------
static __device__ __half g_A1[(size_t)B_SZ * K1];
static __device__ __half g_W1[(size_t)D_HID * K1];
static __device__ float  g_h [(size_t)B_SZ * D_HID];
static __device__ __half g_A2[(size_t)B_SZ * K2];
static __device__ __half g_W2[(size_t)N2PAD * K2];

// ---------------------------------------------------------------------------
// B-spline bases + silu (matches reference recursion)
// ---------------------------------------------------------------------------
__device__ __forceinline__ void kan_bases(float x, float bs[6]) {
    const float h = 2.0f / 3.0f;
    float t[10];
#pragma unroll
    for (int j = 0; j < 10; ++j) t[j] = -1.0f + (float)(j - 3) * h;
    float b[9];
#pragma unroll
    for (int j = 0; j < 9; ++j) b[j] = (x >= t[j] && x < t[j + 1]) ? 1.0f : 0.0f;
#pragma unroll
    for (int k = 1; k <= 3; ++k) {
#pragma unroll
        for (int j = 0; j < 9 - k; ++j) {
            float l = (x - t[j])         * (1.0f / (t[j + k]     - t[j]));
            float r = (t[j + k + 1] - x) * (1.0f / (t[j + k + 1] - t[j + 1]));
            b[j] = l * b[j] + r * b[j + 1];
        }
    }
#pragma unroll
    for (int j = 0; j < 6; ++j) bs[j] = b[j];
}

__device__ __forceinline__ float silu_f(float v) { return v / (1.0f + expf(-v)); }

// ---------------------------------------------------------------------------
// Expansion: 2 features per thread, __half2 stores
// ---------------------------------------------------------------------------
__global__ void expand1_kernel(const float* __restrict__ x) {
    int idx = blockIdx.x * blockDim.x + threadIdx.x;
    if (idx >= B_SZ * (D_IN / 2)) return;
    int b  = idx / (D_IN / 2);
    int i2 = (idx - b * (D_IN / 2)) * 2;
    float2 v = *reinterpret_cast<const float2*>(x + (size_t)b * D_IN + i2);
    float bs0[6], bs1[6];
    kan_bases(v.x, bs0);
    kan_bases(v.y, bs1);
    size_t base = (size_t)b * K1 + i2;
    *reinterpret_cast<__half2*>(&g_A1[base]) =
        __floats2half2_rn(silu_f(v.x), silu_f(v.y));
#pragma unroll
    for (int j = 0; j < 6; ++j)
        *reinterpret_cast<__half2*>(&g_A1[base + (size_t)(j + 1) * D_IN]) =
            __floats2half2_rn(bs0[j], bs1[j]);
}

// ---------------------------------------------------------------------------
// Weight fusion (unchanged; small)
// ---------------------------------------------------------------------------
__global__ void fusew1_kernel(const float* __restrict__ bw,
                              const float* __restrict__ sw,
                              const float* __restrict__ sc) {
    int idx = blockIdx.x * blockDim.x + threadIdx.x;
    if (idx >= D_HID * D_IN) return;
    int o = idx / D_IN;
    int i = idx - o * D_IN;
    size_t base = (size_t)o * K1 + i;
    g_W1[base] = __float2half(bw[idx]);
    float s = sc[idx];
#pragma unroll
    for (int j = 0; j < 6; ++j)
        g_W1[base + (size_t)(j + 1) * D_IN] = __float2half(sw[(size_t)idx * 6 + j] * s);
}

__global__ void fusew2_kernel(const float* __restrict__ bw,
                              const float* __restrict__ sw,
                              const float* __restrict__ sc) {
    int idx = blockIdx.x * blockDim.x + threadIdx.x;
    if (idx >= N2PAD * D_HID) return;
    int o = idx / D_HID;
    int c = idx - o * D_HID;
    size_t base = (size_t)o * K2 + c;
    if (o < D_OUT) {
        size_t widx = (size_t)o * D_HID + c;
        g_W2[base] = __float2half(bw[widx]);
        float s = sc[widx];
#pragma unroll
        for (int j = 0; j < 6; ++j)
            g_W2[base + (size_t)(j + 1) * D_HID] = __float2half(sw[widx * 6 + j] * s);
    } else {
        g_W2[base] = __float2half(0.0f);
#pragma unroll
        for (int j = 0; j < 6; ++j)
            g_W2[base + (size_t)(j + 1) * D_HID] = __float2half(0.0f);
    }
}

// ---------------------------------------------------------------------------
// LayerNorm + expansion: thread t handles cols 2t, 2t+1; __half2 stores
// ---------------------------------------------------------------------------
__global__ void ln_expand2_kernel(const float* __restrict__ gamma,
                                  const float* __restrict__ beta) {
    int row = blockIdx.x;
    int t = threadIdx.x;
    const float* hr = g_h + (size_t)row * D_HID;
    float2 v = *reinterpret_cast<const float2*>(hr + 2 * t);

    __shared__ float red[8];
    float s = v.x + v.y;
#pragma unroll
    for (int o = 16; o; o >>= 1) s += __shfl_down_sync(0xffffffffu, s, o);
    if ((t & 31) == 0) red[t >> 5] = s;
    __syncthreads();
    float tot = 0.0f;
#pragma unroll
    for (int i = 0; i < 8; ++i) tot += red[i];
    float mean = tot * (1.0f / (float)D_HID);
    __syncthreads();

    float d0 = v.x - mean, d1 = v.y - mean;
    float q = d0 * d0 + d1 * d1;
#pragma unroll
    for (int o = 16; o; o >>= 1) q += __shfl_down_sync(0xffffffffu, q, o);
    if ((t & 31) == 0) red[t >> 5] = q;
    __syncthreads();
    float qt = 0.0f;
#pragma unroll
    for (int i = 0; i < 8; ++i) qt += red[i];
    float inv = rsqrtf(qt * (1.0f / (float)D_HID) + 1e-5f);

    const int c = 2 * t;
    float y0 = d0 * inv * gamma[c]     + beta[c];
    float y1 = d1 * inv * gamma[c + 1] + beta[c + 1];
    float bs0[6], bs1[6];
    kan_bases(y0, bs0);
    kan_bases(y1, bs1);
    size_t base = (size_t)row * K2 + c;
    *reinterpret_cast<__half2*>(&g_A2[base]) =
        __floats2half2_rn(silu_f(y0), silu_f(y1));
#pragma unroll
    for (int j = 0; j < 6; ++j)
        *reinterpret_cast<__half2*>(&g_A2[base + (size_t)(j + 1) * D_HID]) =
            __floats2half2_rn(bs0[j], bs1[j]);
}

// ---------------------------------------------------------------------------
// HMMA GEMM, CUTLASS-style: C[M x NV] = A[M x K] * B[N x K]^T
// Block 128x128x64, 128 threads (4 warps), warp tile 64x64 (acc 128 fp32).
// Register double-buffered ldmatrix fragments -> 32 independent HMMAs per
// k16-step per warp feed the tensor pipe from within a single warp.
// 3-stage cp.async ring; 2 CTAs/SM (smem 110.6KB, regs ~215).
// SMEM rows: 128B data + 16B pad = 144B (conflict-free ldmatrix phases).
// ---------------------------------------------------------------------------
#define BM 128
#define BN 128
#define BK 64
#define ROWB 144u
#define STG_B (uint32_t)((BM + BN) * ROWB)   // 36864 B
#define NSTG 3

template <int L>
__global__ __launch_bounds__(128, 2) void gemm_hmma(float* __restrict__ Cparam) {
    constexpr int KK = (L == 1) ? K1 : K2;
    constexpr int NV = (L == 1) ? D_HID : D_OUT;
    constexpr int KT = KK / BK;

    const __half* __restrict__ A  = (L == 1) ? g_A1 : g_A2;
    const __half* __restrict__ Bw = (L == 1) ? g_W1 : g_W2;
    float* __restrict__ C         = (L == 1) ? g_h  : Cparam;

    extern __shared__ __half smh[];
    const uint32_t sbase = (uint32_t)__cvta_generic_to_shared(smh);

    const int tid  = threadIdx.x;
    const int warp = tid >> 5;
    const int lane = tid & 31;
    const int wm = (warp & 1) * 64;
    const int wn = (warp >> 1) * 64;
    const int mb = blockIdx.y;
    const int nb = blockIdx.x;

    const __half* Abase = A  + (size_t)(mb * BM) * KK;
    const __half* Bbase = Bw + (size_t)(nb * BN) * KK;

    auto issue = [&](int kt) {
        const uint32_t sb = sbase + (uint32_t)(kt % NSTG) * STG_B;
        // A: 128 rows x 8 chunks of 16B = 1024 chunks; 8 per thread
#pragma unroll
        for (int i = 0; i < 8; ++i) {
            const int idx = tid + i * 128;
            const int r = idx >> 3, c = idx & 7;
            const void* src = Abase + (size_t)r * KK + kt * BK + c * 8;
            const uint32_t dst = sb + (uint32_t)r * ROWB + (uint32_t)c * 16u;
            asm volatile("cp.async.cg.shared.global [%0], [%1], 16;"
                         :: "r"(dst), "l"(src));
        }
        // B: 128 rows x 8 chunks; 8 per thread
#pragma unroll
        for (int i = 0; i < 8; ++i) {
            const int idx = tid + i * 128;
            const int r = idx >> 3, c = idx & 7;
            const void* src = Bbase + (size_t)r * KK + kt * BK + c * 8;
            const uint32_t dst = sb + (uint32_t)BM * ROWB
                               + (uint32_t)r * ROWB + (uint32_t)c * 16u;
            asm volatile("cp.async.cg.shared.global [%0], [%1], 16;"
                         :: "r"(dst), "l"(src));
        }
        asm volatile("cp.async.commit_group;" ::: "memory");
    };

    const int lrow = lane & 15;
    const int lcb  = (lane >> 4) * 8;

    // fragment loaders (ldmatrix.x4 over 16x16 blocks)
    auto lda = [&](uint32_t (&a)[4][4], uint32_t sb, int ks) {
#pragma unroll
        for (int mt = 0; mt < 4; ++mt) {
            const uint32_t addr = sb + (uint32_t)(wm + mt * 16 + lrow) * ROWB
                                + (uint32_t)(ks * 16 + lcb) * 2u;
            asm volatile("ldmatrix.sync.aligned.m8n8.x4.shared.b16 {%0,%1,%2,%3}, [%4];"
                         : "=r"(a[mt][0]), "=r"(a[mt][1]), "=r"(a[mt][2]), "=r"(a[mt][3])
                         : "r"(addr));
        }
    };
    auto ldb = [&](uint32_t (&b)[4][4], uint32_t sb, int ks) {
#pragma unroll
        for (int np = 0; np < 4; ++np) {
            const uint32_t addr = sb + (uint32_t)BM * ROWB
                                + (uint32_t)(wn + np * 16 + lrow) * ROWB
                                + (uint32_t)(ks * 16 + lcb) * 2u;
            asm volatile("ldmatrix.sync.aligned.m8n8.x4.shared.b16 {%0,%1,%2,%3}, [%4];"
                         : "=r"(b[np][0]), "=r"(b[np][1]), "=r"(b[np][2]), "=r"(b[np][3])
                         : "r"(addr));
        }
    };

    float acc[4][8][4] = {};
    uint32_t af[2][4][4];
    uint32_t bf[2][4][4];

    issue(0); issue(1);

#pragma unroll 1
    for (int kt = 0; kt < KT; ++kt) {
        if (kt + 1 < KT) asm volatile("cp.async.wait_group 1;" ::: "memory");
        else             asm volatile("cp.async.wait_group 0;" ::: "memory");
        __syncthreads();
        if (kt + 2 < KT) issue(kt + 2);

        const uint32_t sb = sbase + (uint32_t)(kt % NSTG) * STG_B;
        lda(af[0], sb, 0);
        ldb(bf[0], sb, 0);
#pragma unroll
        for (int ks = 0; ks < 4; ++ks) {
            const int cur = ks & 1;
            if (ks < 3) {
                lda(af[cur ^ 1], sb, ks + 1);
                ldb(bf[cur ^ 1], sb, ks + 1);
            }
#pragma unroll
            for (int mt = 0; mt < 4; ++mt) {
#pragma unroll
                for (int nt = 0; nt < 8; ++nt) {
                    const int np = nt >> 1, pp = nt & 1;
                    asm volatile(
                        "mma.sync.aligned.m16n8k16.row.col.f32.f16.f16.f32 "
                        "{%0,%1,%2,%3}, {%4,%5,%6,%7}, {%8,%9}, {%0,%1,%2,%3};"
                        : "+f"(acc[mt][nt][0]), "+f"(acc[mt][nt][1]),
                          "+f"(acc[mt][nt][2]), "+f"(acc[mt][nt][3])
                        : "r"(af[cur][mt][0]), "r"(af[cur][mt][1]),
                          "r"(af[cur][mt][2]), "r"(af[cur][mt][3]),
                          "r"(bf[cur][np][pp]), "r"(bf[cur][np][pp + 2]));
                }
            }
        }
    }

    // ---- epilogue ----
    const int gr = lane >> 2;
    const int gc = (lane & 3) * 2;
#pragma unroll
    for (int mt = 0; mt < 4; ++mt) {
#pragma unroll
        for (int nt = 0; nt < 8; ++nt) {
            const int row = mb * BM + wm + mt * 16 + gr;
            const int col = nb * BN + wn + nt * 8 + gc;
            float* cp = C + (size_t)row * NV;
            if (NV % BN == 0) {
                cp[col]     = acc[mt][nt][0];
                cp[col + 1] = acc[mt][nt][1];
                cp += (size_t)8 * NV;
                cp[col]     = acc[mt][nt][2];
                cp[col + 1] = acc[mt][nt][3];
            } else {
                if (col < NV)     cp[col]     = acc[mt][nt][0];
                if (col + 1 < NV) cp[col + 1] = acc[mt][nt][1];
                cp += (size_t)8 * NV;
                if (col < NV)     cp[col]     = acc[mt][nt][2];
                if (col + 1 < NV) cp[col + 1] = acc[mt][nt][3];
            }
        }
    }
}

// ---------------------------------------------------------------------------
// Launch
// ---------------------------------------------------------------------------
#define GEMM_SMEM (NSTG * (int)STG_B)   // 110592 B

extern "C" void kernel_launch(void* const* d_in, const int* in_sizes, int n_in,
                              void* d_out, int out_size) {
    (void)in_sizes; (void)n_in; (void)out_size;
    const float* x   = (const float*)d_in[0];
    const float* bw1 = (const float*)d_in[1];
    const float* sw1 = (const float*)d_in[2];
    const float* sc1 = (const float*)d_in[3];
    const float* ga  = (const float*)d_in[4];
    const float* be  = (const float*)d_in[5];
    const float* bw2 = (const float*)d_in[6];
    const float* sw2 = (const float*)d_in[7];
    const float* sc2 = (const float*)d_in[8];
    float* out = (float*)d_out;

    cudaFuncSetAttribute(gemm_hmma<1>,
                         cudaFuncAttributeMaxDynamicSharedMemorySize, GEMM_SMEM);
    cudaFuncSetAttribute(gemm_hmma<2>,
                         cudaFuncAttributeMaxDynamicSharedMemorySize, GEMM_SMEM);

    fusew1_kernel<<<(D_HID * D_IN + 255) / 256, 256>>>(bw1, sw1, sc1);
    fusew2_kernel<<<(N2PAD * D_HID + 255) / 256, 256>>>(bw2, sw2, sc2);
    expand1_kernel<<<(B_SZ * (D_IN / 2) + 255) / 256, 256>>>(x);

    // GEMM1: N blocks = 512/128 = 4, M blocks = 16384/128 = 128 -> 512 CTAs
    gemm_hmma<1><<<dim3(4, 128), 128, GEMM_SMEM>>>(nullptr);

    ln_expand2_kernel<<<B_SZ, 256>>>(ga, be);

    // GEMM2: N blocks = 256/128 = 2, M blocks = 128 -> 256 CTAs
    gemm_hmma<2><<<dim3(2, 128), 128, GEMM_SMEM>>>(out);
}

// round 7
// speedup vs baseline: 1.0409x; 1.0409x over previous
#include <cuda_runtime.h>
#include <cuda_fp16.h>
#include <stdint.h>
#include <math.h>

// ---------------------------------------------------------------------------
// Problem dims
// ---------------------------------------------------------------------------
#define B_SZ   16384
#define D_IN   1280
#define D_HID  512
#define D_OUT  229
#define K1     (7 * D_IN)    // 8960
#define K2     (7 * D_HID)   // 3584
#define N2PAD  256

// ---------------------------------------------------------------------------
// Scratch
// ---------------------------------------------------------------------------
static __device__ __half g_A1[(size_t)B_SZ * K1];
static __device__ __half g_W1[(size_t)D_HID * K1];
static __device__ float  g_h [(size_t)B_SZ * D_HID];
static __device__ __half g_A2[(size_t)B_SZ * K2];
static __device__ __half g_W2[(size_t)N2PAD * K2];

// ---------------------------------------------------------------------------
// B-spline bases + silu (matches reference recursion)
// ---------------------------------------------------------------------------
__device__ __forceinline__ void kan_bases(float x, float bs[6]) {
    const float h = 2.0f / 3.0f;
    float t[10];
#pragma unroll
    for (int j = 0; j < 10; ++j) t[j] = -1.0f + (float)(j - 3) * h;
    float b[9];
#pragma unroll
    for (int j = 0; j < 9; ++j) b[j] = (x >= t[j] && x < t[j + 1]) ? 1.0f : 0.0f;
#pragma unroll
    for (int k = 1; k <= 3; ++k) {
#pragma unroll
        for (int j = 0; j < 9 - k; ++j) {
            float l = (x - t[j])         * (1.0f / (t[j + k]     - t[j]));
            float r = (t[j + k + 1] - x) * (1.0f / (t[j + k + 1] - t[j + 1]));
            b[j] = l * b[j] + r * b[j + 1];
        }
    }
#pragma unroll
    for (int j = 0; j < 6; ++j) bs[j] = b[j];
}

__device__ __forceinline__ float silu_f(float v) { return v / (1.0f + expf(-v)); }

// ---------------------------------------------------------------------------
// Merged prep kernel: expand1 + fusew1 + fusew2 in one launch.
// Block ranges: [0, E1) expand1 | [E1, E1+F1) fusew1 | [E1+F1, E1+F1+F2) fusew2
// ---------------------------------------------------------------------------
#define E1_BLOCKS (B_SZ * (D_IN / 2) / 256)      // 40960
#define F1_BLOCKS (D_HID * D_IN / 256)            // 2560
#define F2_BLOCKS (N2PAD * D_HID / 256)           // 512
#define PREP_BLOCKS (E1_BLOCKS + F1_BLOCKS + F2_BLOCKS)

__global__ __launch_bounds__(256) void prep_kernel(
    const float* __restrict__ x,
    const float* __restrict__ bw1, const float* __restrict__ sw1,
    const float* __restrict__ sc1,
    const float* __restrict__ bw2, const float* __restrict__ sw2,
    const float* __restrict__ sc2)
{
    const int blk = blockIdx.x;
    if (blk < E1_BLOCKS) {
        // ---- expand1: 2 features per thread, __half2 stores ----
        int idx = blk * 256 + threadIdx.x;
        int b  = idx / (D_IN / 2);
        int i2 = (idx - b * (D_IN / 2)) * 2;
        float2 v = *reinterpret_cast<const float2*>(x + (size_t)b * D_IN + i2);
        float bs0[6], bs1[6];
        kan_bases(v.x, bs0);
        kan_bases(v.y, bs1);
        size_t base = (size_t)b * K1 + i2;
        *reinterpret_cast<__half2*>(&g_A1[base]) =
            __floats2half2_rn(silu_f(v.x), silu_f(v.y));
#pragma unroll
        for (int j = 0; j < 6; ++j)
            *reinterpret_cast<__half2*>(&g_A1[base + (size_t)(j + 1) * D_IN]) =
                __floats2half2_rn(bs0[j], bs1[j]);
    } else if (blk < E1_BLOCKS + F1_BLOCKS) {
        // ---- fusew1 ----
        int idx = (blk - E1_BLOCKS) * 256 + threadIdx.x;
        int o = idx / D_IN;
        int i = idx - o * D_IN;
        size_t base = (size_t)o * K1 + i;
        g_W1[base] = __float2half(bw1[idx]);
        float s = sc1[idx];
#pragma unroll
        for (int j = 0; j < 6; ++j)
            g_W1[base + (size_t)(j + 1) * D_IN] =
                __float2half(sw1[(size_t)idx * 6 + j] * s);
    } else {
        // ---- fusew2 (zero-padded rows o >= D_OUT) ----
        int idx = (blk - E1_BLOCKS - F1_BLOCKS) * 256 + threadIdx.x;
        int o = idx / D_HID;
        int c = idx - o * D_HID;
        size_t base = (size_t)o * K2 + c;
        if (o < D_OUT) {
            size_t widx = (size_t)o * D_HID + c;
            g_W2[base] = __float2half(bw2[widx]);
            float s = sc2[widx];
#pragma unroll
            for (int j = 0; j < 6; ++j)
                g_W2[base + (size_t)(j + 1) * D_HID] =
                    __float2half(sw2[widx * 6 + j] * s);
        } else {
            g_W2[base] = __float2half(0.0f);
#pragma unroll
            for (int j = 0; j < 6; ++j)
                g_W2[base + (size_t)(j + 1) * D_HID] = __float2half(0.0f);
        }
    }
}

// ---------------------------------------------------------------------------
// LayerNorm + expansion: thread t handles cols 2t, 2t+1; __half2 stores
// ---------------------------------------------------------------------------
__global__ __launch_bounds__(256) void ln_expand2_kernel(
    const float* __restrict__ gamma, const float* __restrict__ beta)
{
    int row = blockIdx.x;
    int t = threadIdx.x;
    const float* hr = g_h + (size_t)row * D_HID;
    float2 v = *reinterpret_cast<const float2*>(hr + 2 * t);

    __shared__ float red[8];
    float s = v.x + v.y;
#pragma unroll
    for (int o = 16; o; o >>= 1) s += __shfl_down_sync(0xffffffffu, s, o);
    if ((t & 31) == 0) red[t >> 5] = s;
    __syncthreads();
    float tot = 0.0f;
#pragma unroll
    for (int i = 0; i < 8; ++i) tot += red[i];
    float mean = tot * (1.0f / (float)D_HID);
    __syncthreads();

    float d0 = v.x - mean, d1 = v.y - mean;
    float q = d0 * d0 + d1 * d1;
#pragma unroll
    for (int o = 16; o; o >>= 1) q += __shfl_down_sync(0xffffffffu, q, o);
    if ((t & 31) == 0) red[t >> 5] = q;
    __syncthreads();
    float qt = 0.0f;
#pragma unroll
    for (int i = 0; i < 8; ++i) qt += red[i];
    float inv = rsqrtf(qt * (1.0f / (float)D_HID) + 1e-5f);

    const int c = 2 * t;
    float y0 = d0 * inv * gamma[c]     + beta[c];
    float y1 = d1 * inv * gamma[c + 1] + beta[c + 1];
    float bs0[6], bs1[6];
    kan_bases(y0, bs0);
    kan_bases(y1, bs1);
    size_t base = (size_t)row * K2 + c;
    *reinterpret_cast<__half2*>(&g_A2[base]) =
        __floats2half2_rn(silu_f(y0), silu_f(y1));
#pragma unroll
    for (int j = 0; j < 6; ++j)
        *reinterpret_cast<__half2*>(&g_A2[base + (size_t)(j + 1) * D_HID]) =
            __floats2half2_rn(bs0[j], bs1[j]);
}

// ---------------------------------------------------------------------------
// HMMA GEMM (exact R5 config — best measured: 47.7% tensor, 64 regs):
// Block 128x128x64, 512 threads (16 warps = 4M x 4N), warp tile 32x32.
// 32 warps/SM at 2 CTAs/SM. 3-stage cp.async ring.
// SMEM rows: 128B data + 16B pad = 144B.
// ---------------------------------------------------------------------------
#define BM 128
#define BN 128
#define BK 64
#define ROWB 144u
#define STG_B (uint32_t)((BM + BN) * ROWB)   // 36864 B
#define NSTG 3

template <int L>
__global__ __launch_bounds__(512, 2) void gemm_hmma(float* __restrict__ Cparam) {
    constexpr int KK = (L == 1) ? K1 : K2;
    constexpr int NV = (L == 1) ? D_HID : D_OUT;
    constexpr int KT = KK / BK;

    const __half* __restrict__ A  = (L == 1) ? g_A1 : g_A2;
    const __half* __restrict__ Bw = (L == 1) ? g_W1 : g_W2;
    float* __restrict__ C         = (L == 1) ? g_h  : Cparam;

    extern __shared__ __half smh[];
    const uint32_t sbase = (uint32_t)__cvta_generic_to_shared(smh);

    const int tid  = threadIdx.x;
    const int warp = tid >> 5;
    const int lane = tid & 31;
    const int wm = (warp & 3) * 32;
    const int wn = (warp >> 2) * 32;
    const int mb = blockIdx.y;
    const int nb = blockIdx.x;

    const __half* Abase = A  + (size_t)(mb * BM) * KK;
    const __half* Bbase = Bw + (size_t)(nb * BN) * KK;

    auto issue = [&](int kt) {
        const uint32_t sb = sbase + (uint32_t)(kt % NSTG) * STG_B;
#pragma unroll
        for (int i = 0; i < 2; ++i) {
            const int idx = tid + i * 512;
            const int r = idx >> 3, c = idx & 7;
            const void* src = Abase + (size_t)r * KK + kt * BK + c * 8;
            const uint32_t dst = sb + (uint32_t)r * ROWB + (uint32_t)c * 16u;
            asm volatile("cp.async.cg.shared.global [%0], [%1], 16;"
                         :: "r"(dst), "l"(src));
        }
#pragma unroll
        for (int i = 0; i < 2; ++i) {
            const int idx = tid + i * 512;
            const int r = idx >> 3, c = idx & 7;
            const void* src = Bbase + (size_t)r * KK + kt * BK + c * 8;
            const uint32_t dst = sb + (uint32_t)BM * ROWB
                               + (uint32_t)r * ROWB + (uint32_t)c * 16u;
            asm volatile("cp.async.cg.shared.global [%0], [%1], 16;"
                         :: "r"(dst), "l"(src));
        }
        asm volatile("cp.async.commit_group;" ::: "memory");
    };

    float acc[2][4][4] = {};

    issue(0); issue(1);

    const int lrow = lane & 15;
    const int lcb  = (lane >> 4) * 8;

#pragma unroll 1
    for (int kt = 0; kt < KT; ++kt) {
        if (kt + 1 < KT) asm volatile("cp.async.wait_group 1;" ::: "memory");
        else             asm volatile("cp.async.wait_group 0;" ::: "memory");
        __syncthreads();
        if (kt + 2 < KT) issue(kt + 2);

        const uint32_t sb = sbase + (uint32_t)(kt % NSTG) * STG_B;
#pragma unroll
        for (int ks = 0; ks < 4; ++ks) {
            uint32_t a[2][4];
            uint32_t bq[2][4];
#pragma unroll
            for (int mt = 0; mt < 2; ++mt) {
                const uint32_t addr = sb + (uint32_t)(wm + mt * 16 + lrow) * ROWB
                                    + (uint32_t)(ks * 16 + lcb) * 2u;
                asm volatile("ldmatrix.sync.aligned.m8n8.x4.shared.b16 {%0,%1,%2,%3}, [%4];"
                             : "=r"(a[mt][0]), "=r"(a[mt][1]), "=r"(a[mt][2]), "=r"(a[mt][3])
                             : "r"(addr));
            }
#pragma unroll
            for (int np = 0; np < 2; ++np) {
                const uint32_t addr = sb + (uint32_t)BM * ROWB
                                    + (uint32_t)(wn + np * 16 + lrow) * ROWB
                                    + (uint32_t)(ks * 16 + lcb) * 2u;
                asm volatile("ldmatrix.sync.aligned.m8n8.x4.shared.b16 {%0,%1,%2,%3}, [%4];"
                             : "=r"(bq[np][0]), "=r"(bq[np][1]), "=r"(bq[np][2]), "=r"(bq[np][3])
                             : "r"(addr));
            }
#pragma unroll
            for (int mt = 0; mt < 2; ++mt) {
#pragma unroll
                for (int nt = 0; nt < 4; ++nt) {
                    const int np = nt >> 1, pp = nt & 1;
                    asm volatile(
                        "mma.sync.aligned.m16n8k16.row.col.f32.f16.f16.f32 "
                        "{%0,%1,%2,%3}, {%4,%5,%6,%7}, {%8,%9}, {%0,%1,%2,%3};"
                        : "+f"(acc[mt][nt][0]), "+f"(acc[mt][nt][1]),
                          "+f"(acc[mt][nt][2]), "+f"(acc[mt][nt][3])
                        : "r"(a[mt][0]), "r"(a[mt][1]), "r"(a[mt][2]), "r"(a[mt][3]),
                          "r"(bq[np][pp]), "r"(bq[np][pp + 2]));
                }
            }
        }
    }

    // ---- epilogue ----
    const int gr = lane >> 2;
    const int gc = (lane & 3) * 2;
#pragma unroll
    for (int mt = 0; mt < 2; ++mt) {
#pragma unroll
        for (int nt = 0; nt < 4; ++nt) {
            const int row = mb * BM + wm + mt * 16 + gr;
            const int col = nb * BN + wn + nt * 8 + gc;
            float* cp = C + (size_t)row * NV;
            if (NV % BN == 0) {
                cp[col]     = acc[mt][nt][0];
                cp[col + 1] = acc[mt][nt][1];
                cp += (size_t)8 * NV;
                cp[col]     = acc[mt][nt][2];
                cp[col + 1] = acc[mt][nt][3];
            } else {
                if (col < NV)     cp[col]     = acc[mt][nt][0];
                if (col + 1 < NV) cp[col + 1] = acc[mt][nt][1];
                cp += (size_t)8 * NV;
                if (col < NV)     cp[col]     = acc[mt][nt][2];
                if (col + 1 < NV) cp[col + 1] = acc[mt][nt][3];
            }
        }
    }
}

// ---------------------------------------------------------------------------
// Launch
// ---------------------------------------------------------------------------
#define GEMM_SMEM (NSTG * (int)STG_B)   // 110592 B

extern "C" void kernel_launch(void* const* d_in, const int* in_sizes, int n_in,
                              void* d_out, int out_size) {
    (void)in_sizes; (void)n_in; (void)out_size;
    const float* x   = (const float*)d_in[0];
    const float* bw1 = (const float*)d_in[1];
    const float* sw1 = (const float*)d_in[2];
    const float* sc1 = (const float*)d_in[3];
    const float* ga  = (const float*)d_in[4];
    const float* be  = (const float*)d_in[5];
    const float* bw2 = (const float*)d_in[6];
    const float* sw2 = (const float*)d_in[7];
    const float* sc2 = (const float*)d_in[8];
    float* out = (float*)d_out;

    cudaFuncSetAttribute(gemm_hmma<1>,
                         cudaFuncAttributeMaxDynamicSharedMemorySize, GEMM_SMEM);
    cudaFuncSetAttribute(gemm_hmma<2>,
                         cudaFuncAttributeMaxDynamicSharedMemorySize, GEMM_SMEM);

    // One merged prep launch: expand1 + fusew1 + fusew2
    prep_kernel<<<PREP_BLOCKS, 256>>>(x, bw1, sw1, sc1, bw2, sw2, sc2);

    // GEMM1: N blocks = 512/128 = 4, M blocks = 16384/128 = 128 -> 512 CTAs
    gemm_hmma<1><<<dim3(4, 128), 512, GEMM_SMEM>>>(nullptr);

    ln_expand2_kernel<<<B_SZ, 256>>>(ga, be);

    // GEMM2: N blocks = 256/128 = 2, M blocks = 128 -> 256 CTAs
    gemm_hmma<2><<<dim3(2, 128), 512, GEMM_SMEM>>>(out);
}